// round 8
// baseline (speedup 1.0000x reference)
#include <cuda_runtime.h>
#include <cstdint>

#define NC 32
#define NU 5
#define NV 5
#define NH 64
#define NW 64

#define TILE_H 8
#define ROWF 72                 // smem row pitch (floats): 4 pad | 64 data | 4 pad
#define ROWS 10                 // TILE_H + 2
#define PLF (ROWS * ROWF)       // 720 floats per uv-plane
#define XF (9 * PLF)            // 6480 floats per x stage
#define WU 864                  // duplicated weights per channel (u64 count)
#define WFD (2 * WU)            // 1728 floats per channel (duplicated)
#define STAGEF (XF + WFD)       // 8208 floats per stage
#define SMEM_FLOATS (2 * STAGEF)
#define SMEM_BYTES  (SMEM_FLOATS * 4)   // 65664
#define CHSTRIDE (NU * NV * NH * NW)    // 102400

typedef unsigned long long u64;

// Duplicated weights: u64 per weight (w,w); layout [c][br][half][tap][oc]
// (tap = (ka*3+kb)*3+kg over the branch's own dims, oc = 0..3 within half)
__device__ __align__(128) u64 g_wd[NC * WU];
__device__ float g_bias[32];
__device__ float g_slope[4];

__global__ void prep_kernel(const float* __restrict__ w0, const float* __restrict__ w1,
                            const float* __restrict__ w2, const float* __restrict__ w3,
                            const float* __restrict__ b0, const float* __restrict__ b1,
                            const float* __restrict__ b2, const float* __restrict__ b3,
                            const float* __restrict__ a0, const float* __restrict__ a1,
                            const float* __restrict__ a2, const float* __restrict__ a3)
{
    int t = blockIdx.x * blockDim.x + threadIdx.x;
    if (t < NC * WU) {
        int c    = t / WU;
        int rem  = t - c * WU;        // 0..863
        int br   = rem / 216;
        int rem2 = rem - br * 216;    // 0..215
        int half = rem2 / 108;
        int rem3 = rem2 - half * 108; // 0..107
        int tap  = rem3 >> 2;
        int oc   = rem3 & 3;
        int o    = half * 4 + oc;
        const float* w = (br == 0) ? w0 : (br == 1) ? w1 : (br == 2) ? w2 : w3;
        float val = w[(o * NC + c) * 27 + tap];
        ((float2*)g_wd)[t] = make_float2(val, val);
    }
    if (t < 32) {
        const float* b = (t < 8) ? b0 : (t < 16) ? b1 : (t < 24) ? b2 : b3;
        g_bias[t] = b[t & 7];
    }
    if (t < 4) {
        const float* a = (t == 0) ? a0 : (t == 1) ? a1 : (t == 2) ? a2 : a3;
        g_slope[t] = a[0];
    }
}

// ---------- helpers ----------
__device__ __forceinline__ uint32_t smem_u32(const void* p) {
    uint32_t a;
    asm("{ .reg .u64 t; cvta.to.shared.u64 t, %1; cvt.u32.u64 %0, t; }" : "=r"(a) : "l"(p));
    return a;
}
__device__ __forceinline__ void cp16(uint32_t dst, const void* src) {
    asm volatile("cp.async.cg.shared.global [%0], [%1], 16;" :: "r"(dst), "l"(src) : "memory");
}
__device__ __forceinline__ void cp_commit() {
    asm volatile("cp.async.commit_group;" ::: "memory");
}
__device__ __forceinline__ void cp_wait1() {
    asm volatile("cp.async.wait_group 1;" ::: "memory");
}
__device__ __forceinline__ void cp_wait0() {
    asm volatile("cp.async.wait_group 0;" ::: "memory");
}
__device__ __forceinline__ void fma2(u64& acc, u64 a, u64 b) {
    asm("fma.rn.f32x2 %0, %1, %2, %0;" : "+l"(acc) : "l"(a), "l"(b));
}
__device__ __forceinline__ u64 pack2(uint32_t lo, uint32_t hi) {
    u64 r;
    asm("mov.b64 %0, {%1, %2};" : "=l"(r) : "r"(lo), "r"(hi));
    return r;
}
__device__ __forceinline__ float2 unpack2(u64 v) {
    float2 r;
    asm("mov.b64 {%0, %1}, %2;" : "=f"(r.x), "=f"(r.y) : "l"(v));
    return r;
}

// ---------- staging: one channel (x tile + duplicated weights) ----------
// x: 90 rows (9 uv-planes x 10 h-rows) of 64 floats = 16 chunks each (1440).
// OOB rows skipped (smem pre-zeroed; OOB pattern channel-invariant).
// w: 432 x 16B chunks.
__device__ __forceinline__ void stage_channel(const float* __restrict__ xc, int c,
                                              uint32_t sx_u32, uint32_t sw_u32,
                                              int u, int v, int th, int tid)
{
    #pragma unroll
    for (int i = 0; i < 6; i++) {
        int k = tid + i * 256;
        if (i < 5 || k < 1440) {
            int row   = k >> 4;
            int chunk = k & 15;
            int pidx  = row / 10;
            int r     = row - pidx * 10;
            int pa    = pidx / 3;
            int pb    = pidx - pa * 3;
            int gu = u + pa - 1;
            int gv = v + pb - 1;
            int gh = th + r - 1;
            if ((unsigned)gu < NU && (unsigned)gv < NV && (unsigned)gh < NH) {
                const float* src = xc + (((gu * 5 + gv) * NH + gh) << 6) + chunk * 4;
                uint32_t dst = sx_u32 + (uint32_t)(row * ROWF + 4 + chunk * 4) * 4u;
                cp16(dst, src);
            }
        }
    }
    #pragma unroll
    for (int i = 0; i < 2; i++) {
        int k = tid + i * 256;
        if (k < 432) {
            const char* src = (const char*)(g_wd + (size_t)c * WU) + (size_t)k * 16;
            cp16(sw_u32 + (uint32_t)k * 16u, src);
        }
    }
}

// ===== per-warp compute: one branch, one oc-half =====
// thread covers w = {2wl, 2wl+1}, 8 h-points, 4 oc. acc[p][oc] = f32x2 over w.
// sw64: this warp's 108 u64 weights (tap*4 + oc), each (w,w) duplicated.

// uvx: taps (u, v, h); x pair at center w.
__device__ __forceinline__ void comp_uvx(const float* __restrict__ s_x,
                                         const u64* __restrict__ sw64,
                                         int wl, u64 (&acc)[8][4])
{
    #pragma unroll
    for (int ab = 0; ab < 9; ab++) {
        u64 w[3][4];
        #pragma unroll
        for (int kg = 0; kg < 3; kg++)
            #pragma unroll
            for (int oc = 0; oc < 4; oc++)
                w[kg][oc] = sw64[(ab * 3 + kg) * 4 + oc];
        const float* col = s_x + ab * PLF + 4 + 2 * wl;
        #pragma unroll
        for (int r = 0; r < 10; r++) {
            u64 xB = *(const u64*)(col + r * ROWF);
            #pragma unroll
            for (int kg = 0; kg < 3; kg++) {
                int p = r - kg;
                if (p >= 0 && p < 8) {
                    #pragma unroll
                    for (int oc = 0; oc < 4; oc++)
                        fma2(acc[p][oc], xB, w[kg][oc]);
                }
            }
        }
    }
}

// uvy: taps (u, v, w); h fixed (row p+1); shifted w pairs via recombination.
__device__ __forceinline__ void comp_uvy(const float* __restrict__ s_x,
                                         const u64* __restrict__ sw64,
                                         int wl, u64 (&acc)[8][4])
{
    #pragma unroll
    for (int ab = 0; ab < 9; ab++) {
        u64 w[3][4];
        #pragma unroll
        for (int kg = 0; kg < 3; kg++)
            #pragma unroll
            for (int oc = 0; oc < 4; oc++)
                w[kg][oc] = sw64[(ab * 3 + kg) * 4 + oc];
        const float* plb = s_x + ab * PLF + 2 + 2 * wl;
        #pragma unroll
        for (int p = 0; p < 8; p++) {
            const uint2* rp = (const uint2*)(plb + (p + 1) * ROWF);
            uint2 A = rp[0];
            uint2 B = rp[1];
            uint2 C = rp[2];
            u64 P0 = pack2(A.y, B.x);
            u64 P1 = pack2(B.x, B.y);
            u64 P2 = pack2(B.y, C.x);
            #pragma unroll
            for (int oc = 0; oc < 4; oc++) fma2(acc[p][oc], P0, w[0][oc]);
            #pragma unroll
            for (int oc = 0; oc < 4; oc++) fma2(acc[p][oc], P1, w[1][oc]);
            #pragma unroll
            for (int oc = 0; oc < 4; oc++) fma2(acc[p][oc], P2, w[2][oc]);
        }
    }
}

// uxy (planes (ka,1)) / vxy (planes (1,ka)): taps (*, h, w).
__device__ __forceinline__ void comp_hw(const float* __restrict__ s_x,
                                        const u64* __restrict__ sw64,
                                        int wl, int plane_base, int plane_step,
                                        u64 (&acc)[8][4])
{
    #pragma unroll
    for (int ka = 0; ka < 3; ka++) {
        const float* plb = s_x + (plane_base + ka * plane_step) * PLF + 2 + 2 * wl;
        #pragma unroll
        for (int kg = 0; kg < 3; kg++) {
            u64 w[3][4];
            #pragma unroll
            for (int kb = 0; kb < 3; kb++)
                #pragma unroll
                for (int oc = 0; oc < 4; oc++)
                    w[kb][oc] = sw64[((ka * 3 + kb) * 3 + kg) * 4 + oc];
            #pragma unroll
            for (int r = 0; r < 10; r++) {
                const uint2* rp = (const uint2*)(plb + r * ROWF);
                u64 P;
                if (kg == 0) {
                    uint2 A = rp[0], B = rp[1];
                    P = pack2(A.y, B.x);
                } else if (kg == 1) {
                    uint2 B = rp[1];
                    P = pack2(B.x, B.y);
                } else {
                    uint2 B = rp[1], C = rp[2];
                    P = pack2(B.y, C.x);
                }
                #pragma unroll
                for (int kb = 0; kb < 3; kb++) {
                    int p = r - kb;
                    if (p >= 0 && p < 8) {
                        #pragma unroll
                        for (int oc = 0; oc < 4; oc++)
                            fma2(acc[p][oc], P, w[kb][oc]);
                    }
                }
            }
        }
    }
}

// ===================== main kernel =====================
__global__ __launch_bounds__(256, 2)
void fe_kernel(const float* __restrict__ x, float* __restrict__ out)
{
    extern __shared__ __align__(16) float sm[];
    float* sx0 = sm;
    float* sx1 = sm + STAGEF;
    u64*   sw0 = (u64*)(sm + XF);
    u64*   sw1 = (u64*)(sm + STAGEF + XF);
    const uint32_t sx_u[2] = { smem_u32(sx0), smem_u32(sx1) };
    const uint32_t sw_u[2] = { smem_u32(sw0), smem_u32(sw1) };
    const float* sx_p[2] = { sx0, sx1 };
    const u64*   sw_p[2] = { sw0, sw1 };

    const int tid  = threadIdx.x;
    const int g    = tid >> 5;        // warp 0..7
    const int br   = g >> 1;          // branch 0..3
    const int half = g & 1;           // oc half 0..1
    const int wl   = tid & 31;        // w-pair lane: covers w = 2wl, 2wl+1

    const int th = blockIdx.x * TILE_H;   // 0..56
    const int uv = blockIdx.y;            // 0..24
    const int u  = uv / 5, v = uv % 5;
    const int b  = blockIdx.z;            // 0..7

    // one-time zero (halo cols + channel-invariant OOB rows)
    float4* z = (float4*)sm;
    #pragma unroll
    for (int i = tid; i < SMEM_FLOATS / 4; i += 256)
        z[i] = make_float4(0.f, 0.f, 0.f, 0.f);
    __syncthreads();

    const float* xb = x + (size_t)b * (NC * CHSTRIDE);

    stage_channel(xb, 0, sx_u[0], sw_u[0], u, v, th, tid);
    cp_commit();

    u64 acc[8][4];
    #pragma unroll
    for (int p = 0; p < 8; p++)
        #pragma unroll
        for (int j = 0; j < 4; j++) acc[p][j] = 0ull;

    #pragma unroll 1
    for (int c = 0; c < NC; c++) {
        const int s = c & 1;
        if (c < NC - 1) {
            stage_channel(xb + (size_t)(c + 1) * CHSTRIDE, c + 1,
                          sx_u[s ^ 1], sw_u[s ^ 1], u, v, th, tid);
            cp_commit();
            cp_wait1();
        } else {
            cp_wait0();
        }
        __syncthreads();

        const u64* sw64 = sw_p[s] + (br * 2 + half) * 108;
        if (br == 0)      comp_uvx(sx_p[s], sw64, wl, acc);
        else if (br == 1) comp_uvy(sx_p[s], sw64, wl, acc);
        else if (br == 2) comp_hw(sx_p[s], sw64, wl, 1, 3, acc); // uxy
        else              comp_hw(sx_p[s], sw64, wl, 3, 1, acc); // vxy
        __syncthreads();
    }

    // ---- epilogue: bias + PReLU + vector store (two w per store) ----
    const float slope = g_slope[br];
    const int ocb = br * 8 + half * 4;
    float2* outv = (float2*)(out + (size_t)b * 32 * CHSTRIDE +
                             (size_t)ocb * CHSTRIDE +
                             (size_t)uv * (NH * NW) + (size_t)th * NW) + wl;
    #pragma unroll
    for (int oc = 0; oc < 4; oc++) {
        const float bb = g_bias[ocb + oc];
        float2* po = outv + (size_t)oc * (CHSTRIDE / 2);
        #pragma unroll
        for (int p = 0; p < 8; p++) {
            float2 y = unpack2(acc[p][oc]);
            float y0 = y.x + bb;
            float y1 = y.y + bb;
            y0 = (y0 >= 0.f) ? y0 : slope * y0;
            y1 = (y1 >= 0.f) ? y1 : slope * y1;
            po[(size_t)p * (NW / 2)] = make_float2(y0, y1);
        }
    }
}

extern "C" void kernel_launch(void* const* d_in, const int* in_sizes, int n_in,
                              void* d_out, int out_size)
{
    const float* x = (const float*)d_in[0];

    prep_kernel<<<(NC * WU + 255) / 256, 256>>>(
        (const float*)d_in[1], (const float*)d_in[4],
        (const float*)d_in[7], (const float*)d_in[10],
        (const float*)d_in[2], (const float*)d_in[5],
        (const float*)d_in[8], (const float*)d_in[11],
        (const float*)d_in[3], (const float*)d_in[6],
        (const float*)d_in[9], (const float*)d_in[12]);

    static bool attr_set = false;
    if (!attr_set) {
        cudaFuncSetAttribute(fe_kernel, cudaFuncAttributeMaxDynamicSharedMemorySize,
                             SMEM_BYTES);
        attr_set = true;
    }

    dim3 grid(8, 25, 8);   // (h tiles, uv, batch)
    fe_kernel<<<grid, 256, SMEM_BYTES>>>(x, (float*)d_out);
}

// round 9
// speedup vs baseline: 1.5814x; 1.5814x over previous
#include <cuda_runtime.h>
#include <cstdint>

#define NC 32
#define NU 5
#define NV 5
#define NH 64
#define NW 64

#define TILE_H 4
#define TILE_W 32
#define ROWF 40                 // smem row pitch (floats); col j holds w = tw-4+j
#define ROWS 6                  // TILE_H + 2
#define PLF (ROWS * ROWF)       // 240 floats per uv-plane
#define XF (9 * PLF)            // 2160 floats per x stage
#define WF (4 * 27 * 8)         // 864 weights per channel
#define STAGEF (XF + WF)        // 3024
#define SMEM_FLOATS (2 * STAGEF)
#define CHSTRIDE (NU * NV * NH * NW) // 102400

typedef unsigned long long u64;

// Reorganized weights: [c][branch][tap][o], tap = (ka*3+kb)*3+kg
__device__ __align__(128) float g_wr[NC * WF];
__device__ float g_bias[32];
__device__ float g_slope[4];

__global__ void prep_kernel(const float* __restrict__ w0, const float* __restrict__ w1,
                            const float* __restrict__ w2, const float* __restrict__ w3,
                            const float* __restrict__ b0, const float* __restrict__ b1,
                            const float* __restrict__ b2, const float* __restrict__ b3,
                            const float* __restrict__ a0, const float* __restrict__ a1,
                            const float* __restrict__ a2, const float* __restrict__ a3)
{
    int t = blockIdx.x * blockDim.x + threadIdx.x;
    if (t < NC * WF) {
        int o   = t & 7;
        int tap = (t >> 3) % 27;
        int br  = (t / 216) & 3;
        int c   = t / 864;
        const float* w = (br == 0) ? w0 : (br == 1) ? w1 : (br == 2) ? w2 : w3;
        g_wr[t] = w[(o * NC + c) * 27 + tap];
    }
    if (t < 32) {
        const float* b = (t < 8) ? b0 : (t < 16) ? b1 : (t < 24) ? b2 : b3;
        g_bias[t] = b[t & 7];
    }
    if (t < 4) {
        const float* a = (t == 0) ? a0 : (t == 1) ? a1 : (t == 2) ? a2 : a3;
        g_slope[t] = a[0];
    }
}

// ---------- helpers ----------
__device__ __forceinline__ uint32_t smem_u32(const void* p) {
    uint32_t a;
    asm("{ .reg .u64 t; cvta.to.shared.u64 t, %1; cvt.u32.u64 %0, t; }" : "=r"(a) : "l"(p));
    return a;
}
__device__ __forceinline__ void cp16(uint32_t dst, const void* src) {
    asm volatile("cp.async.cg.shared.global [%0], [%1], 16;" :: "r"(dst), "l"(src) : "memory");
}
__device__ __forceinline__ void cp_commit() {
    asm volatile("cp.async.commit_group;" ::: "memory");
}
__device__ __forceinline__ void cp_wait1() {
    asm volatile("cp.async.wait_group 1;" ::: "memory");
}
__device__ __forceinline__ void cp_wait0() {
    asm volatile("cp.async.wait_group 0;" ::: "memory");
}
__device__ __forceinline__ void fma2(u64& acc, u64 a, u64 b) {
    asm("fma.rn.f32x2 %0, %1, %2, %0;" : "+l"(acc) : "l"(a), "l"(b));
}
__device__ __forceinline__ u64 splat2(float v) {
    u64 r;
    asm("mov.b64 %0, {%1, %1};" : "=l"(r) : "f"(v));
    return r;
}
__device__ __forceinline__ float2 unpack2(u64 v) {
    float2 r;
    asm("mov.b64 {%0, %1}, %2;" : "=f"(r.x), "=f"(r.y) : "l"(v));
    return r;
}

// ---------- staging: one channel (x tile + weights) via cp.async ----------
// x: 54 rows (9 uv-planes x 6 h-rows), 10 x 16B chunks per row = 540.
// smem col j holds global w = tw - 4 + j. OOB chunks skipped (smem pre-zeroed;
// OOB pattern channel-invariant). w: 216 x 16B chunks.
__device__ __forceinline__ void stage_channel(const float* __restrict__ xc, int c,
                                              uint32_t sx_u32, uint32_t sw_u32,
                                              int u, int v, int th, int tw, int tid)
{
    #pragma unroll
    for (int i = 0; i < 5; i++) {
        int k = tid + i * 128;
        if (i < 4 || k < 540) {
            int row   = k / 10;
            int chunk = k - row * 10;
            int pidx  = row / 6;
            int r     = row - pidx * 6;
            int pa    = pidx / 3;
            int pb    = pidx - pa * 3;
            int gu = u + pa - 1;
            int gv = v + pb - 1;
            int gh = th + r - 1;
            int gw = tw - 4 + chunk * 4;
            if ((unsigned)gu < NU && (unsigned)gv < NV && (unsigned)gh < NH &&
                (unsigned)gw < NW) {
                const float* src = xc + (((gu * 5 + gv) * NH + gh) << 6) + gw;
                uint32_t dst = sx_u32 + (uint32_t)(row * ROWF + chunk * 4) * 4u;
                cp16(dst, src);
            }
        }
    }
    #pragma unroll
    for (int i = 0; i < 2; i++) {
        int k = tid + i * 128;
        if (k < 216) {
            const float* src = g_wr + c * WF + k * 4;
            cp16(sw_u32 + (uint32_t)k * 16u, src);
        }
    }
}

// ===== per-warp compute: one branch, 4 h-points x 8 oc per thread =====
// acc[p][j]: h point p, oc pair (2j, 2j+1). x col for center w: wl + 4.

// uvx: taps (u, v, h)
__device__ __forceinline__ void comp_uvx(const float* __restrict__ s_x,
                                         const float* __restrict__ s_w,
                                         int wl, u64 (&acc)[4][4])
{
    #pragma unroll
    for (int ab = 0; ab < 9; ab++) {
        const float* col = s_x + ab * PLF + (wl + 4);
        u64 xs[6];
        #pragma unroll
        for (int r = 0; r < 6; r++) xs[r] = splat2(col[r * ROWF]);
        #pragma unroll
        for (int kg = 0; kg < 3; kg++) {
            const float* wp = s_w + (ab * 3 + kg) * 8;
            ulonglong2 w01 = *(const ulonglong2*)wp;
            ulonglong2 w23 = *(const ulonglong2*)(wp + 4);
            #pragma unroll
            for (int p = 0; p < 4; p++) {
                u64 xx = xs[p + kg];
                fma2(acc[p][0], xx, w01.x);
                fma2(acc[p][1], xx, w01.y);
                fma2(acc[p][2], xx, w23.x);
                fma2(acc[p][3], xx, w23.y);
            }
        }
    }
}

// uvy: taps (u, v, w); row p+1, col wl+3+kg
__device__ __forceinline__ void comp_uvy(const float* __restrict__ s_x,
                                         const float* __restrict__ s_w,
                                         int wl, u64 (&acc)[4][4])
{
    #pragma unroll
    for (int ab = 0; ab < 9; ab++) {
        const float* plb = s_x + ab * PLF;
        #pragma unroll
        for (int kg = 0; kg < 3; kg++) {
            const float* col = plb + (wl + 3 + kg);
            const float* wp = s_w + 216 + (ab * 3 + kg) * 8;
            ulonglong2 w01 = *(const ulonglong2*)wp;
            ulonglong2 w23 = *(const ulonglong2*)(wp + 4);
            #pragma unroll
            for (int p = 0; p < 4; p++) {
                u64 xx = splat2(col[(p + 1) * ROWF]);
                fma2(acc[p][0], xx, w01.x);
                fma2(acc[p][1], xx, w01.y);
                fma2(acc[p][2], xx, w23.x);
                fma2(acc[p][3], xx, w23.y);
            }
        }
    }
}

// uxy (planes (ka,1), wbase 432) / vxy (planes (1,ka), wbase 648):
// taps (*, h, w): row p+kb, col wl+3+kg
__device__ __forceinline__ void comp_hw(const float* __restrict__ s_x,
                                        const float* __restrict__ s_w,
                                        int wl, int plane_base, int plane_step,
                                        int wbase, u64 (&acc)[4][4])
{
    #pragma unroll
    for (int ka = 0; ka < 3; ka++) {
        const float* plb = s_x + (plane_base + ka * plane_step) * PLF;
        #pragma unroll
        for (int kg = 0; kg < 3; kg++) {
            const float* col = plb + (wl + 3 + kg);
            u64 xs[6];
            #pragma unroll
            for (int r = 0; r < 6; r++) xs[r] = splat2(col[r * ROWF]);
            #pragma unroll
            for (int kb = 0; kb < 3; kb++) {
                const float* wp = s_w + wbase + ((ka * 3 + kb) * 3 + kg) * 8;
                ulonglong2 w01 = *(const ulonglong2*)wp;
                ulonglong2 w23 = *(const ulonglong2*)(wp + 4);
                #pragma unroll
                for (int p = 0; p < 4; p++) {
                    u64 xx = xs[p + kb];
                    fma2(acc[p][0], xx, w01.x);
                    fma2(acc[p][1], xx, w01.y);
                    fma2(acc[p][2], xx, w23.x);
                    fma2(acc[p][3], xx, w23.y);
                }
            }
        }
    }
}

// ===================== main kernel =====================
__global__ __launch_bounds__(128, 6)
void fe_kernel(const float* __restrict__ x, float* __restrict__ out)
{
    __shared__ __align__(16) float sm[SMEM_FLOATS];
    float* sx0 = sm;
    float* sx1 = sm + STAGEF;
    float* sw0 = sm + XF;
    float* sw1 = sm + STAGEF + XF;
    const uint32_t sx_u[2] = { smem_u32(sx0), smem_u32(sx1) };
    const uint32_t sw_u[2] = { smem_u32(sw0), smem_u32(sw1) };
    const float* sx_p[2] = { sx0, sx1 };
    const float* sw_p[2] = { sw0, sw1 };

    const int tid = threadIdx.x;
    const int br  = tid >> 5;        // warp = branch 0..3
    const int wl  = tid & 31;        // w lane

    const int tile = blockIdx.x;             // 0..31
    const int tw   = (tile & 1) * TILE_W;
    const int th   = (tile >> 1) * TILE_H;   // 0..60
    const int uv   = blockIdx.y;             // 0..24
    const int u    = uv / 5, v = uv % 5;
    const int b    = blockIdx.z;             // 0..7

    // one-time zero (halo + channel-invariant OOB chunks)
    float4* z = (float4*)sm;
    #pragma unroll
    for (int i = tid; i < SMEM_FLOATS / 4; i += 128)
        z[i] = make_float4(0.f, 0.f, 0.f, 0.f);
    __syncthreads();

    const float* xb = x + (size_t)b * (NC * CHSTRIDE);

    stage_channel(xb, 0, sx_u[0], sw_u[0], u, v, th, tw, tid);
    cp_commit();

    u64 acc[4][4];
    #pragma unroll
    for (int p = 0; p < 4; p++)
        #pragma unroll
        for (int j = 0; j < 4; j++) acc[p][j] = 0ull;

    #pragma unroll 1
    for (int c = 0; c < NC; c++) {
        const int s = c & 1;
        if (c < NC - 1) {
            stage_channel(xb + (size_t)(c + 1) * CHSTRIDE, c + 1,
                          sx_u[s ^ 1], sw_u[s ^ 1], u, v, th, tw, tid);
            cp_commit();
            cp_wait1();
        } else {
            cp_wait0();
        }
        __syncthreads();

        if (br == 0)      comp_uvx(sx_p[s], sw_p[s], wl, acc);
        else if (br == 1) comp_uvy(sx_p[s], sw_p[s], wl, acc);
        else if (br == 2) comp_hw(sx_p[s], sw_p[s], wl, 1, 3, 432, acc); // uxy
        else              comp_hw(sx_p[s], sw_p[s], wl, 3, 1, 648, acc); // vxy
        __syncthreads();
    }

    // ---- epilogue: bias + PReLU + store ----
    const float slope = g_slope[br];
    const int ocb = br * 8;
    const size_t base0 = (size_t)b * 32 * CHSTRIDE + (size_t)ocb * CHSTRIDE +
                         (size_t)uv * (NH * NW) + (size_t)th * NW + (size_t)(tw + wl);
    #pragma unroll
    for (int j = 0; j < 4; j++) {
        const float b0 = g_bias[ocb + j * 2];
        const float b1 = g_bias[ocb + j * 2 + 1];
        const size_t cb0 = base0 + (size_t)(j * 2) * CHSTRIDE;
        const size_t cb1 = base0 + (size_t)(j * 2 + 1) * CHSTRIDE;
        #pragma unroll
        for (int p = 0; p < 4; p++) {
            float2 y = unpack2(acc[p][j]);
            float y0 = y.x + b0;
            float y1 = y.y + b1;
            y0 = (y0 >= 0.f) ? y0 : slope * y0;
            y1 = (y1 >= 0.f) ? y1 : slope * y1;
            out[cb0 + (size_t)p * NW] = y0;
            out[cb1 + (size_t)p * NW] = y1;
        }
    }
}

extern "C" void kernel_launch(void* const* d_in, const int* in_sizes, int n_in,
                              void* d_out, int out_size)
{
    const float* x = (const float*)d_in[0];

    prep_kernel<<<(NC * WF + 255) / 256, 256>>>(
        (const float*)d_in[1], (const float*)d_in[4],
        (const float*)d_in[7], (const float*)d_in[10],
        (const float*)d_in[2], (const float*)d_in[5],
        (const float*)d_in[8], (const float*)d_in[11],
        (const float*)d_in[3], (const float*)d_in[6],
        (const float*)d_in[9], (const float*)d_in[12]);

    dim3 grid(32, 25, 8);   // (hw tiles: 2w x 16h, uv, batch)
    fe_kernel<<<grid, 128>>>(x, (float*)d_out);
}